// round 1
// baseline (speedup 1.0000x reference)
#include <cuda_runtime.h>
#include <cstdint>
#include <math.h>

// Problem constants
#define NROWS 8192
#define CDIM  256

// GEMM tiling
#define BM 128
#define BN 128
#define BK 32
#define LDSS (BK + 4)   // 36 floats: pad -> conflict-free fragment loads, float4-aligned

// Scratch (static device globals only; no allocation allowed)
__device__ float g_fn[NROWS * CDIM];     // normalized features, tf32-rounded (8 MB)
__device__ float g_rowval[NROWS];        // per-row -mean_log_prob_pos

// ---------------------------------------------------------------------------
// K0: L2-normalize each row, round to tf32 for the MMA path.
// ---------------------------------------------------------------------------
__global__ void normalize_kernel(const float* __restrict__ f) {
    int row = blockIdx.x;
    int tid = threadIdx.x;               // 256 threads, one per channel
    float v = f[row * CDIM + tid];
    float s = v * v;
    __shared__ float red[8];
    #pragma unroll
    for (int o = 16; o > 0; o >>= 1) s += __shfl_xor_sync(0xffffffffu, s, o);
    if ((tid & 31) == 0) red[tid >> 5] = s;
    __syncthreads();
    if (tid < 8) {
        float t = red[tid];
        #pragma unroll
        for (int o = 4; o > 0; o >>= 1) t += __shfl_xor_sync(0xffu, t, o);
        if (tid == 0) red[0] = t;
    }
    __syncthreads();
    float norm  = sqrtf(red[0]);
    float scale = 1.0f / fmaxf(norm, 1e-8f);
    float out = v * scale;
    asm("cvt.rna.tf32.f32 %0, %1;" : "=f"(out) : "f"(out));
    g_fn[row * CDIM + tid] = out;
}

// ---------------------------------------------------------------------------
// tf32 mma.sync m16n8k8 (fp32 accumulate)
// ---------------------------------------------------------------------------
__device__ __forceinline__ void mma_tf32(float c[4], const uint32_t a[4], const uint32_t b[2]) {
    asm volatile(
        "mma.sync.aligned.m16n8k8.row.col.f32.tf32.tf32.f32 "
        "{%0,%1,%2,%3}, {%4,%5,%6,%7}, {%8,%9}, {%0,%1,%2,%3};"
        : "+f"(c[0]), "+f"(c[1]), "+f"(c[2]), "+f"(c[3])
        : "r"(a[0]), "r"(a[1]), "r"(a[2]), "r"(a[3]), "r"(b[0]), "r"(b[1]));
}

// ---------------------------------------------------------------------------
// K1: logits = (fn @ fn^T) * 10, plus perfect_logit tile from labels.
// Block computes a 128x128 output tile. 8 warps as 2(M) x 4(N), warp = 64x32.
// ---------------------------------------------------------------------------
__global__ __launch_bounds__(256, 2)
void gemm_kernel(const int* __restrict__ labels,
                 float* __restrict__ out_logits,
                 float* __restrict__ out_perfect) {
    __shared__ float As[BM * LDSS];
    __shared__ float Bs[BN * LDSS];
    __shared__ int   labR[BM];
    __shared__ int   labC[BN];

    const int tid  = threadIdx.x;
    const int lane = tid & 31;
    const int wid  = tid >> 5;
    const int warp_m = wid & 1;          // 0..1
    const int warp_n = wid >> 1;         // 0..3
    const int rowBase = blockIdx.y * BM;
    const int colBase = blockIdx.x * BN;

    if (tid < 128) labR[tid] = labels[rowBase + tid];
    else           labC[tid - 128] = labels[colBase + tid - 128];

    float c[4][4][4];
    #pragma unroll
    for (int mi = 0; mi < 4; mi++)
        #pragma unroll
        for (int ni = 0; ni < 4; ni++)
            #pragma unroll
            for (int q = 0; q < 4; q++) c[mi][ni][q] = 0.0f;

    const int g = lane >> 2;             // groupID   0..7
    const int t = lane & 3;              // thread-in-group 0..3

    for (int kt = 0; kt < CDIM; kt += BK) {
        // Fill tiles: 128x32 floats each; 256 threads x 4 float4 per tile.
        #pragma unroll
        for (int i = 0; i < 4; i++) {
            int f4 = tid + i * 256;              // 0..1023
            int r  = f4 >> 3;                    // row 0..127
            int c4 = (f4 & 7) << 2;              // col 0,4,...,28
            float4 va = *(const float4*)&g_fn[(size_t)(rowBase + r) * CDIM + kt + c4];
            *(float4*)&As[r * LDSS + c4] = va;
            float4 vb = *(const float4*)&g_fn[(size_t)(colBase + r) * CDIM + kt + c4];
            *(float4*)&Bs[r * LDSS + c4] = vb;
        }
        __syncthreads();

        #pragma unroll
        for (int ks = 0; ks < 4; ks++) {
            const int k0 = ks * 8;
            uint32_t a[4][4], b[4][2];
            #pragma unroll
            for (int mi = 0; mi < 4; mi++) {
                int r = warp_m * 64 + mi * 16 + g;
                a[mi][0] = __float_as_uint(As[r * LDSS + k0 + t]);
                a[mi][1] = __float_as_uint(As[(r + 8) * LDSS + k0 + t]);
                a[mi][2] = __float_as_uint(As[r * LDSS + k0 + 4 + t]);
                a[mi][3] = __float_as_uint(As[(r + 8) * LDSS + k0 + 4 + t]);
            }
            #pragma unroll
            for (int ni = 0; ni < 4; ni++) {
                int n = warp_n * 32 + ni * 8 + g;
                b[ni][0] = __float_as_uint(Bs[n * LDSS + k0 + t]);
                b[ni][1] = __float_as_uint(Bs[n * LDSS + k0 + 4 + t]);
            }
            #pragma unroll
            for (int mi = 0; mi < 4; mi++)
                #pragma unroll
                for (int ni = 0; ni < 4; ni++)
                    mma_tf32(c[mi][ni], a[mi], b[ni]);
        }
        __syncthreads();
    }

    // Epilogue: logits (scaled by 1/T = 10). Output region is offset by 1 float,
    // so vector stores would be misaligned -> scalar STG.32 (issue cost is negligible).
    #pragma unroll
    for (int mi = 0; mi < 4; mi++) {
        int r0 = rowBase + warp_m * 64 + mi * 16 + g;
        #pragma unroll
        for (int ni = 0; ni < 4; ni++) {
            int cc = colBase + warp_n * 32 + ni * 8 + 2 * t;
            size_t o0 = (size_t)r0 * NROWS + cc;
            size_t o1 = (size_t)(r0 + 8) * NROWS + cc;
            out_logits[o0]     = c[mi][ni][0] * 10.0f;
            out_logits[o0 + 1] = c[mi][ni][1] * 10.0f;
            out_logits[o1]     = c[mi][ni][2] * 10.0f;
            out_logits[o1 + 1] = c[mi][ni][3] * 10.0f;
        }
    }

    // perfect_logit tile (labels equal -> 1, else -1)
    #pragma unroll 4
    for (int i = 0; i < 64; i++) {
        int idx = tid + i * 256;          // 0..16383
        int rr = idx >> 7;
        int jc = idx & 127;
        out_perfect[(size_t)(rowBase + rr) * NROWS + colBase + jc] =
            (labR[rr] == labC[jc]) ? 1.0f : -1.0f;
    }
}

// ---------------------------------------------------------------------------
// K2: per-row reductions over the written logits.
//   denom_i = sum_{j!=i} exp(l_ij); pos_i = sum_{j!=i, same class} l_ij; cnt_i
//   rowval_i = -(pos_i - cnt_i*log(denom_i)) / (cnt_i + 1e-6)
// ---------------------------------------------------------------------------
__global__ void rowreduce_kernel(const float* __restrict__ logits,
                                 const int* __restrict__ labels) {
    __shared__ int slab[NROWS];          // 32 KB, L2-hot loads
    const int i   = blockIdx.x;
    const int tid = threadIdx.x;         // 256
    for (int j = tid; j < NROWS; j += 256) slab[j] = labels[j];
    __syncthreads();
    const int li = slab[i];
    const float* row = logits + (size_t)i * NROWS;

    float denom = 0.0f, pos = 0.0f, cnt = 0.0f;
    for (int j = tid; j < NROWS; j += 256) {
        float l = row[j];
        if (j != i) {
            denom += __expf(l);
            if (slab[j] == li) { pos += l; cnt += 1.0f; }
        }
    }

    __shared__ float rd[3][8];
    #pragma unroll
    for (int o = 16; o > 0; o >>= 1) {
        denom += __shfl_xor_sync(0xffffffffu, denom, o);
        pos   += __shfl_xor_sync(0xffffffffu, pos,   o);
        cnt   += __shfl_xor_sync(0xffffffffu, cnt,   o);
    }
    if ((tid & 31) == 0) {
        rd[0][tid >> 5] = denom; rd[1][tid >> 5] = pos; rd[2][tid >> 5] = cnt;
    }
    __syncthreads();
    if (tid == 0) {
        float D = 0.f, P = 0.f, Cn = 0.f;
        #pragma unroll
        for (int w = 0; w < 8; w++) { D += rd[0][w]; P += rd[1][w]; Cn += rd[2][w]; }
        float m = (P - Cn * logf(D)) / (Cn + 1e-6f);
        g_rowval[i] = -m;                // TEMPERATURE/BASE_TEMPERATURE == 1
    }
}

// ---------------------------------------------------------------------------
// K3: loss = mean(rowval)
// ---------------------------------------------------------------------------
__global__ void loss_kernel(float* __restrict__ out) {
    const int tid = threadIdx.x;         // 256
    float s = 0.0f;
    for (int i = tid; i < NROWS; i += 256) s += g_rowval[i];
    __shared__ float rd[8];
    #pragma unroll
    for (int o = 16; o > 0; o >>= 1) s += __shfl_xor_sync(0xffffffffu, s, o);
    if ((tid & 31) == 0) rd[tid >> 5] = s;
    __syncthreads();
    if (tid == 0) {
        float tot = 0.f;
        #pragma unroll
        for (int w = 0; w < 8; w++) tot += rd[w];
        out[0] = tot / (float)NROWS;
    }
}

// ---------------------------------------------------------------------------
// Launch: out layout = [loss(1) | logits(8192^2) | perfect_logit(8192^2)]
// ---------------------------------------------------------------------------
extern "C" void kernel_launch(void* const* d_in, const int* in_sizes, int n_in,
                              void* d_out, int out_size) {
    const float* features = (const float*)d_in[0];
    const int*   labels   = (const int*)d_in[1];
    float* out         = (float*)d_out;
    float* out_logits  = out + 1;
    float* out_perfect = out + 1 + (size_t)NROWS * NROWS;

    normalize_kernel<<<NROWS, 256>>>(features);
    dim3 grid(NROWS / BN, NROWS / BM);
    gemm_kernel<<<grid, 256>>>(labels, out_logits, out_perfect);
    rowreduce_kernel<<<NROWS, 256>>>(out_logits, labels);
    loss_kernel<<<1, 256>>>(out);
}

// round 4
// speedup vs baseline: 1.8147x; 1.8147x over previous
#include <cuda_runtime.h>
#include <cstdint>
#include <math.h>

#define NROWS 8192
#define CDIM  256

// GEMM tiling: 128x128 tile per CTA, K pipelined in chunks of 16.
#define BM 128
#define BN 128
#define BK 16
#define NKT (CDIM / BK)          // 16 k-tiles
#define NCOLB (NROWS / BN)       // 64 column blocks
#define NROWB (NROWS / BM)       // 64 row blocks

// Device scratch (static globals; no allocation allowed)
// g_fnA: fragment-order layout for the A operand:
//   block (R=row/16, K8=k/8) -> 128 floats at ((R*32+K8)*128);
//   lane L=(g*4+t) holds {A[g][t], A[g+8][t], A[g][t+4], A[g+8][t+4]} at 4L..4L+3
// g_fnB: fragment-order layout for the B operand:
//   block (N8=row/8, K8=k/8) -> 64 floats at ((N8*32+K8)*64);
//   lane L=(g*4+t) holds {B[n=g][k=t], B[n=g][k=t+4]} at 2L..2L+1
__device__ __align__(1024) float g_fnA[NROWS * CDIM];
__device__ __align__(1024) float g_fnB[NROWS * CDIM];
__device__ float g_denp[NCOLB * NROWS];
__device__ float g_posp[NCOLB * NROWS];
__device__ float g_cntp[NCOLB * NROWS];
__device__ float g_rowval[NROWS];

__device__ __forceinline__ uint32_t smem_u32(const void* p) {
    uint32_t a;
    asm("{ .reg .u64 t; cvta.to.shared.u64 t, %1; cvt.u32.u64 %0, t; }" : "=r"(a) : "l"(p));
    return a;
}
__device__ __forceinline__ void cp_async16(uint32_t s, const void* g) {
    asm volatile("cp.async.ca.shared.global [%0], [%1], 16;" :: "r"(s), "l"(g));
}
#define CP_COMMIT() asm volatile("cp.async.commit_group;" ::: "memory")
#define CP_WAIT(n)  asm volatile("cp.async.wait_group %0;" :: "n"(n) : "memory")

__device__ __forceinline__ void mma_tf32(float c[4], const uint32_t a[4], const uint32_t b[2]) {
    asm volatile(
        "mma.sync.aligned.m16n8k8.row.col.f32.tf32.tf32.f32 "
        "{%0,%1,%2,%3}, {%4,%5,%6,%7}, {%8,%9}, {%0,%1,%2,%3};"
        : "+f"(c[0]), "+f"(c[1]), "+f"(c[2]), "+f"(c[3])
        : "r"(a[0]), "r"(a[1]), "r"(a[2]), "r"(a[3]), "r"(b[0]), "r"(b[1]));
}

// ---------------------------------------------------------------------------
// K0: L2-normalize rows, tf32-round, write both fragment-order copies.
// ---------------------------------------------------------------------------
__global__ void normalize_kernel(const float* __restrict__ f) {
    int row = blockIdx.x;
    int tid = threadIdx.x;               // 256 threads = channels (k index)
    float v = f[row * CDIM + tid];
    float s = v * v;
    __shared__ float red[8];
    #pragma unroll
    for (int o = 16; o > 0; o >>= 1) s += __shfl_xor_sync(0xffffffffu, s, o);
    if ((tid & 31) == 0) red[tid >> 5] = s;
    __syncthreads();
    if (tid < 8) {
        float t = red[tid];
        #pragma unroll
        for (int o = 4; o > 0; o >>= 1) t += __shfl_xor_sync(0xffu, t, o);
        if (tid == 0) red[0] = t;
    }
    __syncthreads();
    float scale = 1.0f / fmaxf(sqrtf(red[0]), 1e-8f);
    float out = v * scale;
    asm("cvt.rna.tf32.f32 %0, %1;" : "=f"(out) : "f"(out));

    int k = tid;
    int K8 = k >> 3, k8i = k & 7, t = k8i & 3, hi = k8i >> 2;
    // A-perm
    {
        int R = row >> 4, g2 = row & 15, gg = g2 & 7, wh = g2 >> 3;
        g_fnA[(size_t)(R * 32 + K8) * 128 + (gg * 4 + t) * 4 + hi * 2 + wh] = out;
    }
    // B-perm
    {
        int N8 = row >> 3, g = row & 7;
        g_fnB[(size_t)(N8 * 32 + K8) * 64 + (g * 4 + t) * 2 + hi] = out;
    }
}

// ---------------------------------------------------------------------------
// K1: tf32 mma.sync GEMM, cp.async double-buffered, fused epilogue:
//   logits*10 stores, perfect_logit, per-(colblock,row) denom/pos/cnt partials.
//   8 warps as 2(M) x 4(N); warp tile 64x32. Partials are reduced across the
//   4 warp_n column-slices through shared memory (race fix vs R3).
// ---------------------------------------------------------------------------
__global__ __launch_bounds__(256, 2)
void gemm_tc(const int* __restrict__ labels,
             float* __restrict__ out_logits,
             float* __restrict__ out_perfect) {
    // stage s: A = 8 Rblk x 2 K8 x 128 floats (8KB); B = 16 N8 x 2 K8 x 64 floats (8KB)
    __shared__ float sA[2][2048];
    __shared__ float sB[2][2048];
    __shared__ int   labR[BM];
    __shared__ int   labC[BN];
    __shared__ float sred[4][3][BM];     // [warp_n][den/pos/cnt][row]

    const int tid  = threadIdx.x;
    const int lane = tid & 31;
    const int wid  = tid >> 5;
    const int warp_m = wid & 1;
    const int warp_n = wid >> 1;
    const int rowBase = blockIdx.y * BM;
    const int colBase = blockIdx.x * BN;
    const int g = lane >> 2, t = lane & 3;

    if (tid < 128) labR[tid] = labels[rowBase + tid];
    else           labC[tid - 128] = labels[colBase + tid - 128];

    float c[4][4][4];
    #pragma unroll
    for (int mi = 0; mi < 4; mi++)
        #pragma unroll
        for (int ni = 0; ni < 4; ni++)
            #pragma unroll
            for (int q = 0; q < 4; q++) c[mi][ni][q] = 0.0f;

    const int rB16 = rowBase >> 4;
    const int cB8  = colBase >> 3;

    auto fill = [&](int s, int kt) {
        uint32_t sAu = smem_u32(&sA[s][0]);
        uint32_t sBu = smem_u32(&sB[s][0]);
        #pragma unroll
        for (int i = 0; i < 2; i++) {
            int ca = tid + i * 256;               // A: 512 chunks of 16B
            int blk = ca >> 5, w = ca & 31;
            int gblk = (rB16 + (blk >> 1)) * 32 + kt * 2 + (blk & 1);
            cp_async16(sAu + blk * 512 + w * 16,
                       (const char*)g_fnA + (size_t)gblk * 512 + w * 16);
            int cb = tid + i * 256;               // B: 512 chunks of 16B
            int bblk = cb >> 4, bw = cb & 15;
            int gbb = (cB8 + (bblk >> 1)) * 32 + kt * 2 + (bblk & 1);
            cp_async16(sBu + bblk * 256 + bw * 16,
                       (const char*)g_fnB + (size_t)gbb * 256 + bw * 16);
        }
    };

    fill(0, 0); CP_COMMIT();
    fill(1, 1); CP_COMMIT();

    #pragma unroll 1
    for (int kt = 0; kt < NKT; kt++) {
        if (kt < NKT - 1) { CP_WAIT(1); } else { CP_WAIT(0); }
        __syncthreads();
        const int s = kt & 1;
        #pragma unroll
        for (int ks = 0; ks < 2; ks++) {
            uint32_t a[4][4], b[4][2];
            #pragma unroll
            for (int mi = 0; mi < 4; mi++) {
                const float4 va = *(const float4*)&sA[s][((warp_m * 4 + mi) * 2 + ks) * 128 + lane * 4];
                a[mi][0] = __float_as_uint(va.x); a[mi][1] = __float_as_uint(va.y);
                a[mi][2] = __float_as_uint(va.z); a[mi][3] = __float_as_uint(va.w);
            }
            #pragma unroll
            for (int ni = 0; ni < 4; ni++) {
                const float2 vb = *(const float2*)&sB[s][((warp_n * 4 + ni) * 2 + ks) * 64 + lane * 2];
                b[ni][0] = __float_as_uint(vb.x); b[ni][1] = __float_as_uint(vb.y);
            }
            #pragma unroll
            for (int mi = 0; mi < 4; mi++)
                #pragma unroll
                for (int ni = 0; ni < 4; ni++)
                    mma_tf32(c[mi][ni], a[mi], b[ni]);
        }
        __syncthreads();
        if (kt + 2 < NKT) { fill(kt & 1, kt + 2); CP_COMMIT(); }
    }

    // ---------------- Fused epilogue ----------------
    #pragma unroll
    for (int mi = 0; mi < 4; mi++) {
        const int r0l = warp_m * 64 + mi * 16 + g;
        const int r1l = r0l + 8;
        const int gr0 = rowBase + r0l, gr1 = rowBase + r1l;
        const int lab0 = labR[r0l], lab1 = labR[r1l];
        float d0 = 0.f, p0 = 0.f, n0 = 0.f, d1 = 0.f, p1 = 0.f, n1 = 0.f;
        #pragma unroll
        for (int ni = 0; ni < 4; ni++) {
            const int cl = warp_n * 32 + ni * 8 + 2 * t;
            const int gc = colBase + cl;
            const float v00 = c[mi][ni][0] * 10.0f, v01 = c[mi][ni][1] * 10.0f;
            const float v10 = c[mi][ni][2] * 10.0f, v11 = c[mi][ni][3] * 10.0f;
            out_logits[(size_t)gr0 * NROWS + gc]     = v00;
            out_logits[(size_t)gr0 * NROWS + gc + 1] = v01;
            out_logits[(size_t)gr1 * NROWS + gc]     = v10;
            out_logits[(size_t)gr1 * NROWS + gc + 1] = v11;
            const int lc0 = labC[cl], lc1 = labC[cl + 1];
            if (gc != gr0)     { d0 += __expf(v00); if (lc0 == lab0) { p0 += v00; n0 += 1.f; } }
            if (gc + 1 != gr0) { d0 += __expf(v01); if (lc1 == lab0) { p0 += v01; n0 += 1.f; } }
            if (gc != gr1)     { d1 += __expf(v10); if (lc0 == lab1) { p1 += v10; n1 += 1.f; } }
            if (gc + 1 != gr1) { d1 += __expf(v11); if (lc1 == lab1) { p1 += v11; n1 += 1.f; } }
        }
        #pragma unroll
        for (int o = 1; o <= 2; o <<= 1) {
            d0 += __shfl_xor_sync(0xffffffffu, d0, o);
            p0 += __shfl_xor_sync(0xffffffffu, p0, o);
            n0 += __shfl_xor_sync(0xffffffffu, n0, o);
            d1 += __shfl_xor_sync(0xffffffffu, d1, o);
            p1 += __shfl_xor_sync(0xffffffffu, p1, o);
            n1 += __shfl_xor_sync(0xffffffffu, n1, o);
        }
        // Per-warp_n partial into shared (rows disjoint across warp_m halves).
        if (t == 0) {
            sred[warp_n][0][r0l] = d0; sred[warp_n][1][r0l] = p0; sred[warp_n][2][r0l] = n0;
            sred[warp_n][0][r1l] = d1; sred[warp_n][1][r1l] = p1; sred[warp_n][2][r1l] = n1;
        }
    }
    __syncthreads();

    // Cross-warp_n reduction: one deterministic global slot per (colblock,row).
    if (tid < BM) {
        float D = 0.f, P = 0.f, C = 0.f;
        #pragma unroll
        for (int wn = 0; wn < 4; wn++) {
            D += sred[wn][0][tid];
            P += sred[wn][1][tid];
            C += sred[wn][2][tid];
        }
        const size_t slot = (size_t)blockIdx.x * NROWS + rowBase + tid;
        g_denp[slot] = D; g_posp[slot] = P; g_cntp[slot] = C;
    }

    // perfect_logit tile: 128x128, 64 coalesced stores/thread
    #pragma unroll 8
    for (int i = 0; i < 64; i++) {
        int idx = tid + i * 256;
        int rr = idx >> 7;
        int jc = idx & 127;
        out_perfect[(size_t)(rowBase + rr) * NROWS + colBase + jc] =
            (labR[rr] == labC[jc]) ? 1.0f : -1.0f;
    }
}

// ---------------------------------------------------------------------------
// K2: reduce partials -> per-row value (deterministic order).
// ---------------------------------------------------------------------------
__global__ void rowfinal_kernel() {
    int i = blockIdx.x * 256 + threadIdx.x;      // 32 blocks x 256 = 8192
    float D = 0.f, P = 0.f, C = 0.f;
    #pragma unroll 4
    for (int b = 0; b < NCOLB; b++) {
        D += g_denp[(size_t)b * NROWS + i];
        P += g_posp[(size_t)b * NROWS + i];
        C += g_cntp[(size_t)b * NROWS + i];
    }
    g_rowval[i] = -(P - C * logf(D)) / (C + 1e-6f);
}

// ---------------------------------------------------------------------------
// K3: loss = mean(rowval)
// ---------------------------------------------------------------------------
__global__ void loss_kernel(float* __restrict__ out) {
    const int tid = threadIdx.x;                 // 1024
    float s = 0.0f;
    for (int i = tid; i < NROWS; i += 1024) s += g_rowval[i];
    __shared__ float rd[32];
    #pragma unroll
    for (int o = 16; o > 0; o >>= 1) s += __shfl_xor_sync(0xffffffffu, s, o);
    if ((tid & 31) == 0) rd[tid >> 5] = s;
    __syncthreads();
    if (tid < 32) {
        float v = rd[tid];
        #pragma unroll
        for (int o = 16; o > 0; o >>= 1) v += __shfl_xor_sync(0xffffffffu, v, o);
        if (tid == 0) out[0] = v / (float)NROWS;
    }
}

// ---------------------------------------------------------------------------
// Launch: out = [loss(1) | logits(8192^2) | perfect_logit(8192^2)]
// ---------------------------------------------------------------------------
extern "C" void kernel_launch(void* const* d_in, const int* in_sizes, int n_in,
                              void* d_out, int out_size) {
    const float* features = (const float*)d_in[0];
    const int*   labels   = (const int*)d_in[1];
    float* out         = (float*)d_out;
    float* out_logits  = out + 1;
    float* out_perfect = out + 1 + (size_t)NROWS * NROWS;

    normalize_kernel<<<NROWS, 256>>>(features);
    dim3 grid(NCOLB, NROWB);                     // 64 x 64
    gemm_tc<<<grid, 256>>>(labels, out_logits, out_perfect);
    rowfinal_kernel<<<NROWS / 256, 256>>>();
    loss_kernel<<<1, 1024>>>(out);
}

// round 5
// speedup vs baseline: 2.1647x; 1.1929x over previous
#include <cuda_runtime.h>
#include <cstdint>
#include <math.h>

#define NROWS 8192
#define CDIM  256

#define BM 128
#define BN 128
#define BK 16
#define NKT (CDIM / BK)          // 16 k-tiles
#define NCOLB (NROWS / BN)       // 64
#define NROWB (NROWS / BM)       // 64

// Fragment-order operand layouts (see R3/R4 comments).
__device__ __align__(1024) float g_fnA[NROWS * CDIM];
__device__ __align__(1024) float g_fnB[NROWS * CDIM];
__device__ float g_denp[NCOLB * NROWS];
__device__ float g_posp[NCOLB * NROWS];
__device__ float g_cntp[NCOLB * NROWS];
__device__ float g_rowval[NROWS];

__device__ __forceinline__ uint32_t smem_u32(const void* p) {
    uint32_t a;
    asm("{ .reg .u64 t; cvta.to.shared.u64 t, %1; cvt.u32.u64 %0, t; }" : "=r"(a) : "l"(p));
    return a;
}
__device__ __forceinline__ void cp_async16(uint32_t s, const void* g) {
    asm volatile("cp.async.ca.shared.global [%0], [%1], 16;" :: "r"(s), "l"(g));
}
#define CP_COMMIT() asm volatile("cp.async.commit_group;" ::: "memory")
#define CP_WAIT(n)  asm volatile("cp.async.wait_group %0;" :: "n"(n) : "memory")

__device__ __forceinline__ void mma_tf32(float c[4], const uint32_t a[4], const uint32_t b[2]) {
    asm volatile(
        "mma.sync.aligned.m16n8k8.row.col.f32.tf32.tf32.f32 "
        "{%0,%1,%2,%3}, {%4,%5,%6,%7}, {%8,%9}, {%0,%1,%2,%3};"
        : "+f"(c[0]), "+f"(c[1]), "+f"(c[2]), "+f"(c[3])
        : "r"(a[0]), "r"(a[1]), "r"(a[2]), "r"(a[3]), "r"(b[0]), "r"(b[1]));
}

// ---------------------------------------------------------------------------
// K0: L2-normalize rows, tf32-round, write both fragment-order copies.
// ---------------------------------------------------------------------------
__global__ void normalize_kernel(const float* __restrict__ f) {
    int row = blockIdx.x;
    int tid = threadIdx.x;               // 256 threads = channels (k index)
    float v = f[row * CDIM + tid];
    float s = v * v;
    __shared__ float red[8];
    #pragma unroll
    for (int o = 16; o > 0; o >>= 1) s += __shfl_xor_sync(0xffffffffu, s, o);
    if ((tid & 31) == 0) red[tid >> 5] = s;
    __syncthreads();
    if (tid < 8) {
        float t = red[tid];
        #pragma unroll
        for (int o = 4; o > 0; o >>= 1) t += __shfl_xor_sync(0xffu, t, o);
        if (tid == 0) red[0] = t;
    }
    __syncthreads();
    float scale = 1.0f / fmaxf(sqrtf(red[0]), 1e-8f);
    float out = v * scale;
    asm("cvt.rna.tf32.f32 %0, %1;" : "=f"(out) : "f"(out));

    int k = tid;
    int K8 = k >> 3, k8i = k & 7, t = k8i & 3, hi = k8i >> 2;
    {   // A-perm
        int R = row >> 4, g2 = row & 15, gg = g2 & 7, wh = g2 >> 3;
        g_fnA[(size_t)(R * 32 + K8) * 128 + (gg * 4 + t) * 4 + hi * 2 + wh] = out;
    }
    {   // B-perm
        int N8 = row >> 3, g = row & 7;
        g_fnB[(size_t)(N8 * 32 + K8) * 64 + (g * 4 + t) * 2 + hi] = out;
    }
}

// ---------------------------------------------------------------------------
// K1: symmetric tf32 GEMM. Only upper-triangular CTA tiles (I<=J) compute.
// Off-diagonal CTAs write tile + mirrored tile, and produce row-partials
// (slot [J][I-rows]) plus column-partials (slot [I][J-rows]). Deterministic,
// race-free: every partial slot has exactly one producer.
// ---------------------------------------------------------------------------
__global__ __launch_bounds__(256, 2)
void gemm_tc(const int* __restrict__ labels,
             float* __restrict__ out_logits,
             float* __restrict__ out_perfect) {
    const int J = blockIdx.x;            // colblock
    const int I = blockIdx.y;            // rowblock
    if (J < I) return;                   // lower triangle: no-op
    const bool isDiag = (I == J);

    __shared__ float sA[2][2048];
    __shared__ float sB[2][2048];
    __shared__ int   labR[BM];
    __shared__ int   labC[BN];
    __shared__ float sred[4][3][BM];     // row partials: [warp_n][q][row]
    __shared__ float sredC[2][3][BN];    // col partials: [warp_m][q][col]

    const int tid  = threadIdx.x;
    const int lane = tid & 31;
    const int wid  = tid >> 5;
    const int warp_m = wid & 1;
    const int warp_n = wid >> 1;
    const int rowBase = I * BM;
    const int colBase = J * BN;
    const int g = lane >> 2, t = lane & 3;

    if (tid < 128) labR[tid] = labels[rowBase + tid];
    else           labC[tid - 128] = labels[colBase + tid - 128];

    float c[4][4][4];
    #pragma unroll
    for (int mi = 0; mi < 4; mi++)
        #pragma unroll
        for (int ni = 0; ni < 4; ni++)
            #pragma unroll
            for (int q = 0; q < 4; q++) c[mi][ni][q] = 0.0f;

    const int rB16 = rowBase >> 4;
    const int cB8  = colBase >> 3;

    auto fill = [&](int s, int kt) {
        uint32_t sAu = smem_u32(&sA[s][0]);
        uint32_t sBu = smem_u32(&sB[s][0]);
        #pragma unroll
        for (int i = 0; i < 2; i++) {
            int ca = tid + i * 256;
            int blk = ca >> 5, w = ca & 31;
            int gblk = (rB16 + (blk >> 1)) * 32 + kt * 2 + (blk & 1);
            cp_async16(sAu + blk * 512 + w * 16,
                       (const char*)g_fnA + (size_t)gblk * 512 + w * 16);
            int bblk = ca >> 4, bw = ca & 15;
            int gbb = (cB8 + (bblk >> 1)) * 32 + kt * 2 + (bblk & 1);
            cp_async16(sBu + bblk * 256 + bw * 16,
                       (const char*)g_fnB + (size_t)gbb * 256 + bw * 16);
        }
    };

    fill(0, 0); CP_COMMIT();
    fill(1, 1); CP_COMMIT();

    #pragma unroll 1
    for (int kt = 0; kt < NKT; kt++) {
        if (kt < NKT - 1) { CP_WAIT(1); } else { CP_WAIT(0); }
        __syncthreads();
        const int s = kt & 1;
        #pragma unroll
        for (int ks = 0; ks < 2; ks++) {
            uint32_t a[4][4], b[4][2];
            #pragma unroll
            for (int mi = 0; mi < 4; mi++) {
                const float4 va = *(const float4*)&sA[s][((warp_m * 4 + mi) * 2 + ks) * 128 + lane * 4];
                a[mi][0] = __float_as_uint(va.x); a[mi][1] = __float_as_uint(va.y);
                a[mi][2] = __float_as_uint(va.z); a[mi][3] = __float_as_uint(va.w);
            }
            #pragma unroll
            for (int ni = 0; ni < 4; ni++) {
                const float2 vb = *(const float2*)&sB[s][((warp_n * 4 + ni) * 2 + ks) * 64 + lane * 2];
                b[ni][0] = __float_as_uint(vb.x); b[ni][1] = __float_as_uint(vb.y);
            }
            #pragma unroll
            for (int mi = 0; mi < 4; mi++)
                #pragma unroll
                for (int ni = 0; ni < 4; ni++)
                    mma_tf32(c[mi][ni], a[mi], b[ni]);
        }
        __syncthreads();
        if (kt + 2 < NKT) { fill(kt & 1, kt + 2); CP_COMMIT(); }
    }

    // ---------------- Fused epilogue ----------------
    float cD[4][2], cP[4][2], cC[4][2];      // column partials (off-diag only)
    #pragma unroll
    for (int ni = 0; ni < 4; ni++)
        #pragma unroll
        for (int q = 0; q < 2; q++) { cD[ni][q] = 0.f; cP[ni][q] = 0.f; cC[ni][q] = 0.f; }

    #pragma unroll
    for (int mi = 0; mi < 4; mi++) {
        const int r0l = warp_m * 64 + mi * 16 + g;
        const int r1l = r0l + 8;
        const int gr0 = rowBase + r0l, gr1 = rowBase + r1l;
        const int lab0 = labR[r0l], lab1 = labR[r1l];
        float d0 = 0.f, p0 = 0.f, n0 = 0.f, d1 = 0.f, p1 = 0.f, n1 = 0.f;
        #pragma unroll
        for (int ni = 0; ni < 4; ni++) {
            const int cl = warp_n * 32 + ni * 8 + 2 * t;
            const int gc = colBase + cl;
            const float v00 = c[mi][ni][0] * 10.0f, v01 = c[mi][ni][1] * 10.0f;
            const float v10 = c[mi][ni][2] * 10.0f, v11 = c[mi][ni][3] * 10.0f;
            out_logits[(size_t)gr0 * NROWS + gc]     = v00;
            out_logits[(size_t)gr0 * NROWS + gc + 1] = v01;
            out_logits[(size_t)gr1 * NROWS + gc]     = v10;
            out_logits[(size_t)gr1 * NROWS + gc + 1] = v11;
            const int lc0 = labC[cl], lc1 = labC[cl + 1];
            const float e00 = __expf(v00), e01 = __expf(v01);
            const float e10 = __expf(v10), e11 = __expf(v11);
            if (gc != gr0)     { d0 += e00; if (lc0 == lab0) { p0 += v00; n0 += 1.f; } }
            if (gc + 1 != gr0) { d0 += e01; if (lc1 == lab0) { p0 += v01; n0 += 1.f; } }
            if (gc != gr1)     { d1 += e10; if (lc0 == lab1) { p1 += v10; n1 += 1.f; } }
            if (gc + 1 != gr1) { d1 += e11; if (lc1 == lab1) { p1 += v11; n1 += 1.f; } }
            if (!isDiag) {
                // mirror logits stores (tile [J-rows][I-cols])
                out_logits[(size_t)gc * NROWS + gr0]       = v00;
                out_logits[(size_t)(gc + 1) * NROWS + gr0] = v01;
                out_logits[(size_t)gc * NROWS + gr1]       = v10;
                out_logits[(size_t)(gc + 1) * NROWS + gr1] = v11;
                // column partials (no diagonal elements on off-diag tiles)
                cD[ni][0] += e00 + e10;
                cD[ni][1] += e01 + e11;
                if (lc0 == lab0) { cP[ni][0] += v00; cC[ni][0] += 1.f; }
                if (lc0 == lab1) { cP[ni][0] += v10; cC[ni][0] += 1.f; }
                if (lc1 == lab0) { cP[ni][1] += v01; cC[ni][1] += 1.f; }
                if (lc1 == lab1) { cP[ni][1] += v11; cC[ni][1] += 1.f; }
            }
        }
        #pragma unroll
        for (int o = 1; o <= 2; o <<= 1) {
            d0 += __shfl_xor_sync(0xffffffffu, d0, o);
            p0 += __shfl_xor_sync(0xffffffffu, p0, o);
            n0 += __shfl_xor_sync(0xffffffffu, n0, o);
            d1 += __shfl_xor_sync(0xffffffffu, d1, o);
            p1 += __shfl_xor_sync(0xffffffffu, p1, o);
            n1 += __shfl_xor_sync(0xffffffffu, n1, o);
        }
        if (t == 0) {
            sred[warp_n][0][r0l] = d0; sred[warp_n][1][r0l] = p0; sred[warp_n][2][r0l] = n0;
            sred[warp_n][0][r1l] = d1; sred[warp_n][1][r1l] = p1; sred[warp_n][2][r1l] = n1;
        }
    }

    if (!isDiag) {
        // reduce col partials over g (lane bits 2..4)
        #pragma unroll
        for (int ni = 0; ni < 4; ni++)
            #pragma unroll
            for (int q = 0; q < 2; q++) {
                #pragma unroll
                for (int o = 4; o <= 16; o <<= 1) {
                    cD[ni][q] += __shfl_xor_sync(0xffffffffu, cD[ni][q], o);
                    cP[ni][q] += __shfl_xor_sync(0xffffffffu, cP[ni][q], o);
                    cC[ni][q] += __shfl_xor_sync(0xffffffffu, cC[ni][q], o);
                }
            }
        if (lane < 4) {      // g == 0 lanes (lane == t)
            #pragma unroll
            for (int ni = 0; ni < 4; ni++) {
                int cl = warp_n * 32 + ni * 8 + 2 * t;
                sredC[warp_m][0][cl]     = cD[ni][0];
                sredC[warp_m][1][cl]     = cP[ni][0];
                sredC[warp_m][2][cl]     = cC[ni][0];
                sredC[warp_m][0][cl + 1] = cD[ni][1];
                sredC[warp_m][1][cl + 1] = cP[ni][1];
                sredC[warp_m][2][cl + 1] = cC[ni][1];
            }
        }
    }
    __syncthreads();

    if (tid < BM) {
        float D = 0.f, P = 0.f, C = 0.f;
        #pragma unroll
        for (int wn = 0; wn < 4; wn++) {
            D += sred[wn][0][tid]; P += sred[wn][1][tid]; C += sred[wn][2][tid];
        }
        const size_t slot = (size_t)J * NROWS + rowBase + tid;
        g_denp[slot] = D; g_posp[slot] = P; g_cntp[slot] = C;
    } else if (!isDiag) {
        const int jc = tid - 128;
        const float D = sredC[0][0][jc] + sredC[1][0][jc];
        const float P = sredC[0][1][jc] + sredC[1][1][jc];
        const float C = sredC[0][2][jc] + sredC[1][2][jc];
        const size_t slot = (size_t)I * NROWS + colBase + jc;
        g_denp[slot] = D; g_posp[slot] = P; g_cntp[slot] = C;
    }

    // perfect_logit tile(s)
    #pragma unroll 8
    for (int i = 0; i < 64; i++) {
        int idx = tid + i * 256;
        int rr = idx >> 7;
        int jc = idx & 127;
        float v = (labR[rr] == labC[jc]) ? 1.0f : -1.0f;
        out_perfect[(size_t)(rowBase + rr) * NROWS + colBase + jc] = v;
    }
    if (!isDiag) {
        #pragma unroll 8
        for (int i = 0; i < 64; i++) {
            int idx = tid + i * 256;
            int rr = idx >> 7;       // row in J block
            int jc = idx & 127;      // col in I block
            float v = (labC[rr] == labR[jc]) ? 1.0f : -1.0f;
            out_perfect[(size_t)(colBase + rr) * NROWS + rowBase + jc] = v;
        }
    }
}

// ---------------------------------------------------------------------------
// K2: reduce partials -> per-row value (deterministic order).
// ---------------------------------------------------------------------------
__global__ void rowfinal_kernel() {
    int i = blockIdx.x * 256 + threadIdx.x;
    float D = 0.f, P = 0.f, C = 0.f;
    #pragma unroll 4
    for (int b = 0; b < NCOLB; b++) {
        D += g_denp[(size_t)b * NROWS + i];
        P += g_posp[(size_t)b * NROWS + i];
        C += g_cntp[(size_t)b * NROWS + i];
    }
    g_rowval[i] = -(P - C * logf(D)) / (C + 1e-6f);
}

// ---------------------------------------------------------------------------
// K3: loss = mean(rowval)
// ---------------------------------------------------------------------------
__global__ void loss_kernel(float* __restrict__ out) {
    const int tid = threadIdx.x;                 // 1024
    float s = 0.0f;
    for (int i = tid; i < NROWS; i += 1024) s += g_rowval[i];
    __shared__ float rd[32];
    #pragma unroll
    for (int o = 16; o > 0; o >>= 1) s += __shfl_xor_sync(0xffffffffu, s, o);
    if ((tid & 31) == 0) rd[tid >> 5] = s;
    __syncthreads();
    if (tid < 32) {
        float v = rd[tid];
        #pragma unroll
        for (int o = 16; o > 0; o >>= 1) v += __shfl_xor_sync(0xffffffffu, v, o);
        if (tid == 0) out[0] = v / (float)NROWS;
    }
}

// ---------------------------------------------------------------------------
// Launch: out = [loss(1) | logits(8192^2) | perfect_logit(8192^2)]
// ---------------------------------------------------------------------------
extern "C" void kernel_launch(void* const* d_in, const int* in_sizes, int n_in,
                              void* d_out, int out_size) {
    const float* features = (const float*)d_in[0];
    const int*   labels   = (const int*)d_in[1];
    float* out         = (float*)d_out;
    float* out_logits  = out + 1;
    float* out_perfect = out + 1 + (size_t)NROWS * NROWS;

    normalize_kernel<<<NROWS, 256>>>(features);
    dim3 grid(NCOLB, NROWB);                     // 64 x 64, lower triangle exits
    gemm_tc<<<grid, 256>>>(labels, out_logits, out_perfect);
    rowfinal_kernel<<<NROWS / 256, 256>>>();
    loss_kernel<<<1, 1024>>>(out);
}

// round 6
// speedup vs baseline: 2.6605x; 1.2290x over previous
#include <cuda_runtime.h>
#include <cstdint>
#include <math.h>

#define NROWS 8192
#define CDIM  256

#define BM 128
#define BN 128
#define BK 16
#define NKT (CDIM / BK)          // 16 k-tiles
#define NCOLB (NROWS / BN)       // 64
#define NROWB (NROWS / BM)       // 64

// Fragment-order operand layouts (see earlier rounds).
__device__ __align__(1024) float g_fnA[NROWS * CDIM];
__device__ __align__(1024) float g_fnB[NROWS * CDIM];
__device__ float g_denp[NCOLB * NROWS];
__device__ float g_posp[NCOLB * NROWS];
__device__ float g_cntp[NCOLB * NROWS];
__device__ float g_rowval[NROWS];

__device__ __forceinline__ uint32_t smem_u32(const void* p) {
    uint32_t a;
    asm("{ .reg .u64 t; cvta.to.shared.u64 t, %1; cvt.u32.u64 %0, t; }" : "=r"(a) : "l"(p));
    return a;
}
__device__ __forceinline__ void cp_async16(uint32_t s, const void* g) {
    asm volatile("cp.async.ca.shared.global [%0], [%1], 16;" :: "r"(s), "l"(g));
}
#define CP_COMMIT() asm volatile("cp.async.commit_group;" ::: "memory")
#define CP_WAIT(n)  asm volatile("cp.async.wait_group %0;" :: "n"(n) : "memory")

__device__ __forceinline__ void mma_tf32(float c[4], const uint32_t a[4], const uint32_t b[2]) {
    asm volatile(
        "mma.sync.aligned.m16n8k8.row.col.f32.tf32.tf32.f32 "
        "{%0,%1,%2,%3}, {%4,%5,%6,%7}, {%8,%9}, {%0,%1,%2,%3};"
        : "+f"(c[0]), "+f"(c[1]), "+f"(c[2]), "+f"(c[3])
        : "r"(a[0]), "r"(a[1]), "r"(a[2]), "r"(a[3]), "r"(b[0]), "r"(b[1]));
}

// ---------------------------------------------------------------------------
// K0: L2-normalize rows, tf32-round, write both fragment-order copies.
// ---------------------------------------------------------------------------
__global__ void normalize_kernel(const float* __restrict__ f) {
    int row = blockIdx.x;
    int tid = threadIdx.x;               // 256 threads = channels (k index)
    float v = f[row * CDIM + tid];
    float s = v * v;
    __shared__ float red[8];
    #pragma unroll
    for (int o = 16; o > 0; o >>= 1) s += __shfl_xor_sync(0xffffffffu, s, o);
    if ((tid & 31) == 0) red[tid >> 5] = s;
    __syncthreads();
    if (tid < 8) {
        float t = red[tid];
        #pragma unroll
        for (int o = 4; o > 0; o >>= 1) t += __shfl_xor_sync(0xffu, t, o);
        if (tid == 0) red[0] = t;
    }
    __syncthreads();
    float scale = 1.0f / fmaxf(sqrtf(red[0]), 1e-8f);
    float out = v * scale;
    asm("cvt.rna.tf32.f32 %0, %1;" : "=f"(out) : "f"(out));

    int k = tid;
    int K8 = k >> 3, k8i = k & 7, t = k8i & 3, hi = k8i >> 2;
    {   // A-perm
        int R = row >> 4, g2 = row & 15, gg = g2 & 7, wh = g2 >> 3;
        g_fnA[(size_t)(R * 32 + K8) * 128 + (gg * 4 + t) * 4 + hi * 2 + wh] = out;
    }
    {   // B-perm
        int N8 = row >> 3, g = row & 7;
        g_fnB[(size_t)(N8 * 32 + K8) * 64 + (g * 4 + t) * 2 + hi] = out;
    }
}

// ---------------------------------------------------------------------------
// K1: symmetric tf32 GEMM, upper-triangular CTA tiles only. All logit stores
// staged through shared memory for full coalescing (direct + mirror tiles).
// ---------------------------------------------------------------------------
__global__ __launch_bounds__(256, 2)
void gemm_tc(const int* __restrict__ labels,
             float* __restrict__ out_logits,
             float* __restrict__ out_perfect) {
    const int J = blockIdx.x;            // colblock
    const int I = blockIdx.y;            // rowblock
    if (J < I) return;                   // lower triangle: no-op
    const bool isDiag = (I == J);

    // sbuf serves double duty:
    //   mainloop: sA stage s = sbuf + s*2048; sB stage s = sbuf + 4096 + s*2048
    //   epilogue: 64x132 staging tile (8448 floats)
    __shared__ float sbuf[8448];
    __shared__ int   labR[BM];
    __shared__ int   labC[BN];
    __shared__ float sred[4][3][BM];     // row partials: [warp_n][q][row]
    __shared__ float sredC[2][3][BN];    // col partials: [warp_m][q][col]

    const int tid  = threadIdx.x;
    const int lane = tid & 31;
    const int wid  = tid >> 5;
    const int warp_m = wid & 1;
    const int warp_n = wid >> 1;
    const int rowBase = I * BM;
    const int colBase = J * BN;
    const int g = lane >> 2, t = lane & 3;

    if (tid < 128) labR[tid] = labels[rowBase + tid];
    else           labC[tid - 128] = labels[colBase + tid - 128];

    float c[4][4][4];
    #pragma unroll
    for (int mi = 0; mi < 4; mi++)
        #pragma unroll
        for (int ni = 0; ni < 4; ni++)
            #pragma unroll
            for (int q = 0; q < 4; q++) c[mi][ni][q] = 0.0f;

    const int rB16 = rowBase >> 4;
    const int cB8  = colBase >> 3;

    auto fill = [&](int s, int kt) {
        uint32_t sAu = smem_u32(&sbuf[s * 2048]);
        uint32_t sBu = smem_u32(&sbuf[4096 + s * 2048]);
        #pragma unroll
        for (int i = 0; i < 2; i++) {
            int ca = tid + i * 256;
            int blk = ca >> 5, w = ca & 31;
            int gblk = (rB16 + (blk >> 1)) * 32 + kt * 2 + (blk & 1);
            cp_async16(sAu + blk * 512 + w * 16,
                       (const char*)g_fnA + (size_t)gblk * 512 + w * 16);
            int bblk = ca >> 4, bw = ca & 15;
            int gbb = (cB8 + (bblk >> 1)) * 32 + kt * 2 + (bblk & 1);
            cp_async16(sBu + bblk * 256 + bw * 16,
                       (const char*)g_fnB + (size_t)gbb * 256 + bw * 16);
        }
    };

    fill(0, 0); CP_COMMIT();
    fill(1, 1); CP_COMMIT();

    #pragma unroll 1
    for (int kt = 0; kt < NKT; kt++) {
        if (kt < NKT - 1) { CP_WAIT(1); } else { CP_WAIT(0); }
        __syncthreads();
        const int s = kt & 1;
        #pragma unroll
        for (int ks = 0; ks < 2; ks++) {
            uint32_t a[4][4], b[4][2];
            #pragma unroll
            for (int mi = 0; mi < 4; mi++) {
                const float4 va = *(const float4*)&sbuf[s * 2048 + ((warp_m * 4 + mi) * 2 + ks) * 128 + lane * 4];
                a[mi][0] = __float_as_uint(va.x); a[mi][1] = __float_as_uint(va.y);
                a[mi][2] = __float_as_uint(va.z); a[mi][3] = __float_as_uint(va.w);
            }
            #pragma unroll
            for (int ni = 0; ni < 4; ni++) {
                const float2 vb = *(const float2*)&sbuf[4096 + s * 2048 + ((warp_n * 4 + ni) * 2 + ks) * 64 + lane * 2];
                b[ni][0] = __float_as_uint(vb.x); b[ni][1] = __float_as_uint(vb.y);
            }
            #pragma unroll
            for (int mi = 0; mi < 4; mi++)
                #pragma unroll
                for (int ni = 0; ni < 4; ni++)
                    mma_tf32(c[mi][ni], a[mi], b[ni]);
        }
        __syncthreads();
        if (kt + 2 < NKT) { fill(kt & 1, kt + 2); CP_COMMIT(); }
    }

    // ---------------- Fused epilogue ----------------
    // Scale logits in place once.
    #pragma unroll
    for (int mi = 0; mi < 4; mi++)
        #pragma unroll
        for (int ni = 0; ni < 4; ni++)
            #pragma unroll
            for (int q = 0; q < 4; q++) c[mi][ni][q] *= 10.0f;

    float cD[4][2], cP[4][2], cC[4][2];      // column partials (off-diag only)
    #pragma unroll
    for (int ni = 0; ni < 4; ni++)
        #pragma unroll
        for (int q = 0; q < 2; q++) { cD[ni][q] = 0.f; cP[ni][q] = 0.f; cC[ni][q] = 0.f; }

    #pragma unroll
    for (int mi = 0; mi < 4; mi++) {
        const int r0l = warp_m * 64 + mi * 16 + g;
        const int r1l = r0l + 8;
        const int gr0 = rowBase + r0l, gr1 = rowBase + r1l;
        const int lab0 = labR[r0l], lab1 = labR[r1l];
        float d0 = 0.f, p0 = 0.f, n0 = 0.f, d1 = 0.f, p1 = 0.f, n1 = 0.f;
        #pragma unroll
        for (int ni = 0; ni < 4; ni++) {
            const int cl = warp_n * 32 + ni * 8 + 2 * t;
            const int gc = colBase + cl;
            const float v00 = c[mi][ni][0], v01 = c[mi][ni][1];
            const float v10 = c[mi][ni][2], v11 = c[mi][ni][3];
            const int lc0 = labC[cl], lc1 = labC[cl + 1];
            const float e00 = __expf(v00), e01 = __expf(v01);
            const float e10 = __expf(v10), e11 = __expf(v11);
            if (gc != gr0)     { d0 += e00; if (lc0 == lab0) { p0 += v00; n0 += 1.f; } }
            if (gc + 1 != gr0) { d0 += e01; if (lc1 == lab0) { p0 += v01; n0 += 1.f; } }
            if (gc != gr1)     { d1 += e10; if (lc0 == lab1) { p1 += v10; n1 += 1.f; } }
            if (gc + 1 != gr1) { d1 += e11; if (lc1 == lab1) { p1 += v11; n1 += 1.f; } }
            if (!isDiag) {
                cD[ni][0] += e00 + e10;
                cD[ni][1] += e01 + e11;
                if (lc0 == lab0) { cP[ni][0] += v00; cC[ni][0] += 1.f; }
                if (lc0 == lab1) { cP[ni][0] += v10; cC[ni][0] += 1.f; }
                if (lc1 == lab0) { cP[ni][1] += v01; cC[ni][1] += 1.f; }
                if (lc1 == lab1) { cP[ni][1] += v11; cC[ni][1] += 1.f; }
            }
        }
        #pragma unroll
        for (int o = 1; o <= 2; o <<= 1) {
            d0 += __shfl_xor_sync(0xffffffffu, d0, o);
            p0 += __shfl_xor_sync(0xffffffffu, p0, o);
            n0 += __shfl_xor_sync(0xffffffffu, n0, o);
            d1 += __shfl_xor_sync(0xffffffffu, d1, o);
            p1 += __shfl_xor_sync(0xffffffffu, p1, o);
            n1 += __shfl_xor_sync(0xffffffffu, n1, o);
        }
        if (t == 0) {
            sred[warp_n][0][r0l] = d0; sred[warp_n][1][r0l] = p0; sred[warp_n][2][r0l] = n0;
            sred[warp_n][0][r1l] = d1; sred[warp_n][1][r1l] = p1; sred[warp_n][2][r1l] = n1;
        }
    }

    if (!isDiag) {
        #pragma unroll
        for (int ni = 0; ni < 4; ni++)
            #pragma unroll
            for (int q = 0; q < 2; q++) {
                #pragma unroll
                for (int o = 4; o <= 16; o <<= 1) {
                    cD[ni][q] += __shfl_xor_sync(0xffffffffu, cD[ni][q], o);
                    cP[ni][q] += __shfl_xor_sync(0xffffffffu, cP[ni][q], o);
                    cC[ni][q] += __shfl_xor_sync(0xffffffffu, cC[ni][q], o);
                }
            }
        if (lane < 4) {      // g == 0 lanes
            #pragma unroll
            for (int ni = 0; ni < 4; ni++) {
                int cl = warp_n * 32 + ni * 8 + 2 * t;
                sredC[warp_m][0][cl]     = cD[ni][0];
                sredC[warp_m][1][cl]     = cP[ni][0];
                sredC[warp_m][2][cl]     = cC[ni][0];
                sredC[warp_m][0][cl + 1] = cD[ni][1];
                sredC[warp_m][1][cl + 1] = cP[ni][1];
                sredC[warp_m][2][cl + 1] = cC[ni][1];
            }
        }
    }
    __syncthreads();

    if (tid < BM) {
        float D = 0.f, P = 0.f, C = 0.f;
        #pragma unroll
        for (int wn = 0; wn < 4; wn++) {
            D += sred[wn][0][tid]; P += sred[wn][1][tid]; C += sred[wn][2][tid];
        }
        const size_t slot = (size_t)J * NROWS + rowBase + tid;
        g_denp[slot] = D; g_posp[slot] = P; g_cntp[slot] = C;
    } else if (!isDiag) {
        const int jc = tid - 128;
        const float D = sredC[0][0][jc] + sredC[1][0][jc];
        const float P = sredC[0][1][jc] + sredC[1][1][jc];
        const float C = sredC[0][2][jc] + sredC[1][2][jc];
        const size_t slot = (size_t)I * NROWS + colBase + jc;
        g_denp[slot] = D; g_posp[slot] = P; g_cntp[slot] = C;
    }

    // ---- Direct logits tile via smem staging: coalesced stores ----
    #pragma unroll 1
    for (int h = 0; h < 2; h++) {
        __syncthreads();
        if (warp_m == h) {
            #pragma unroll
            for (int mi = 0; mi < 4; mi++)
                #pragma unroll
                for (int ni = 0; ni < 4; ni++)
                    #pragma unroll
                    for (int q = 0; q < 4; q++) {
                        int rl = mi * 16 + g + 8 * (q >> 1);
                        int cl = warp_n * 32 + ni * 8 + 2 * t + (q & 1);
                        sbuf[rl * 132 + cl] = c[mi][ni][q];
                    }
        }
        __syncthreads();
        #pragma unroll 8
        for (int it = 0; it < 32; it++) {
            int idx = tid + it * 256;
            int rr = idx >> 7, cc = idx & 127;
            out_logits[(size_t)(rowBase + h * 64 + rr) * NROWS + colBase + cc] = sbuf[rr * 132 + cc];
        }
    }

    // ---- Mirror logits tile (transposed) via smem staging ----
    if (!isDiag) {
        #pragma unroll 1
        for (int p = 0; p < 2; p++) {
            __syncthreads();
            if ((warp_n >> 1) == p) {
                #pragma unroll
                for (int mi = 0; mi < 4; mi++)
                    #pragma unroll
                    for (int ni = 0; ni < 4; ni++)
                        #pragma unroll
                        for (int q = 0; q < 4; q++) {
                            int cl = (warp_n & 1) * 32 + ni * 8 + 2 * t + (q & 1);
                            int rl = warp_m * 64 + mi * 16 + g + 8 * (q >> 1);
                            sbuf[cl * 132 + rl] = c[mi][ni][q];
                        }
            }
            __syncthreads();
            #pragma unroll 8
            for (int it = 0; it < 32; it++) {
                int idx = tid + it * 256;
                int rr = idx >> 7, cc = idx & 127;
                out_logits[(size_t)(colBase + p * 64 + rr) * NROWS + rowBase + cc] = sbuf[rr * 132 + cc];
            }
        }
    }

    // perfect_logit tile(s) — already coalesced
    #pragma unroll 8
    for (int i = 0; i < 64; i++) {
        int idx = tid + i * 256;
        int rr = idx >> 7;
        int jc = idx & 127;
        out_perfect[(size_t)(rowBase + rr) * NROWS + colBase + jc] =
            (labR[rr] == labC[jc]) ? 1.0f : -1.0f;
    }
    if (!isDiag) {
        #pragma unroll 8
        for (int i = 0; i < 64; i++) {
            int idx = tid + i * 256;
            int rr = idx >> 7;
            int jc = idx & 127;
            out_perfect[(size_t)(colBase + rr) * NROWS + rowBase + jc] =
                (labC[rr] == labR[jc]) ? 1.0f : -1.0f;
        }
    }
}

// ---------------------------------------------------------------------------
// K2: reduce partials -> per-row value (deterministic order).
// ---------------------------------------------------------------------------
__global__ void rowfinal_kernel() {
    int i = blockIdx.x * 256 + threadIdx.x;
    float D = 0.f, P = 0.f, C = 0.f;
    #pragma unroll 4
    for (int b = 0; b < NCOLB; b++) {
        D += g_denp[(size_t)b * NROWS + i];
        P += g_posp[(size_t)b * NROWS + i];
        C += g_cntp[(size_t)b * NROWS + i];
    }
    g_rowval[i] = -(P - C * logf(D)) / (C + 1e-6f);
}

// ---------------------------------------------------------------------------
// K3: loss = mean(rowval)
// ---------------------------------------------------------------------------
__global__ void loss_kernel(float* __restrict__ out) {
    const int tid = threadIdx.x;                 // 1024
    float s = 0.0f;
    for (int i = tid; i < NROWS; i += 1024) s += g_rowval[i];
    __shared__ float rd[32];
    #pragma unroll
    for (int o = 16; o > 0; o >>= 1) s += __shfl_xor_sync(0xffffffffu, s, o);
    if ((tid & 31) == 0) rd[tid >> 5] = s;
    __syncthreads();
    if (tid < 32) {
        float v = rd[tid];
        #pragma unroll
        for (int o = 16; o > 0; o >>= 1) v += __shfl_xor_sync(0xffffffffu, v, o);
        if (tid == 0) out[0] = v / (float)NROWS;
    }
}

// ---------------------------------------------------------------------------
// Launch: out = [loss(1) | logits(8192^2) | perfect_logit(8192^2)]
// ---------------------------------------------------------------------------
extern "C" void kernel_launch(void* const* d_in, const int* in_sizes, int n_in,
                              void* d_out, int out_size) {
    const float* features = (const float*)d_in[0];
    const int*   labels   = (const int*)d_in[1];
    float* out         = (float*)d_out;
    float* out_logits  = out + 1;
    float* out_perfect = out + 1 + (size_t)NROWS * NROWS;

    normalize_kernel<<<NROWS, 256>>>(features);
    dim3 grid(NCOLB, NROWB);                     // 64 x 64, lower triangle exits
    gemm_tc<<<grid, 256>>>(labels, out_logits, out_perfect);
    rowfinal_kernel<<<NROWS / 256, 256>>>();
    loss_kernel<<<1, 1024>>>(out);
}

// round 7
// speedup vs baseline: 3.2854x; 1.2349x over previous
#include <cuda_runtime.h>
#include <cuda_fp16.h>
#include <cstdint>
#include <math.h>

#define NROWS 8192
#define CDIM  256

#define BM 128
#define BN 128
#define BK 32
#define NKT (CDIM / BK)          // 8 k-tiles
#define NCOLB (NROWS / BN)       // 64
#define NROWB (NROWS / BM)       // 64

// Fragment-order fp16 operand layouts (m16n8k16 fragments):
// A: block (R=row/16, K16=k/16) -> 128 uint32 (256 half) at (R*16+K16)*128;
//    lane L=g*4+t, slot s=hi*2+wh: halfIdx = (blk*128 + L*4 + s)*2 + lo
//    where row = R*16 + wh*8 + g, k = K16*16 + hi*8 + 2t + lo
// B: block (N8=n/8, K16=k/16) -> 64 uint32 at (N8*16+K16)*64;
//    lane L=g*4+t, slot hi: halfIdx = (blk*64 + L*2 + hi)*2 + lo
//    where n = N8*8 + g, k = K16*16 + hi*8 + 2t + lo
__device__ __align__(1024) __half g_fnA[NROWS * CDIM];
__device__ __align__(1024) __half g_fnB[NROWS * CDIM];
__device__ float g_denp[NCOLB * NROWS];
__device__ float g_posp[NCOLB * NROWS];
__device__ float g_cntp[NCOLB * NROWS];
__device__ float g_rowval[NROWS];

__device__ __forceinline__ uint32_t smem_u32(const void* p) {
    uint32_t a;
    asm("{ .reg .u64 t; cvta.to.shared.u64 t, %1; cvt.u32.u64 %0, t; }" : "=r"(a) : "l"(p));
    return a;
}
__device__ __forceinline__ void cp_async16(uint32_t s, const void* g) {
    asm volatile("cp.async.ca.shared.global [%0], [%1], 16;" :: "r"(s), "l"(g));
}
#define CP_COMMIT() asm volatile("cp.async.commit_group;" ::: "memory")
#define CP_WAIT(n)  asm volatile("cp.async.wait_group %0;" :: "n"(n) : "memory")

__device__ __forceinline__ void mma_f16(float c[4], const uint32_t a[4], const uint32_t b[2]) {
    asm volatile(
        "mma.sync.aligned.m16n8k16.row.col.f32.f16.f16.f32 "
        "{%0,%1,%2,%3}, {%4,%5,%6,%7}, {%8,%9}, {%0,%1,%2,%3};"
        : "+f"(c[0]), "+f"(c[1]), "+f"(c[2]), "+f"(c[3])
        : "r"(a[0]), "r"(a[1]), "r"(a[2]), "r"(a[3]), "r"(b[0]), "r"(b[1]));
}

// ---------------------------------------------------------------------------
// K0: L2-normalize rows, convert to fp16, write both fragment-order copies.
// ---------------------------------------------------------------------------
__global__ void normalize_kernel(const float* __restrict__ f) {
    int row = blockIdx.x;
    int tid = threadIdx.x;               // 256 threads = channels (k index)
    float v = f[row * CDIM + tid];
    float s = v * v;
    __shared__ float red[8];
    #pragma unroll
    for (int o = 16; o > 0; o >>= 1) s += __shfl_xor_sync(0xffffffffu, s, o);
    if ((tid & 31) == 0) red[tid >> 5] = s;
    __syncthreads();
    if (tid < 8) {
        float t = red[tid];
        #pragma unroll
        for (int o = 4; o > 0; o >>= 1) t += __shfl_xor_sync(0xffu, t, o);
        if (tid == 0) red[0] = t;
    }
    __syncthreads();
    float scale = 1.0f / fmaxf(sqrtf(red[0]), 1e-8f);
    __half h = __float2half_rn(v * scale);

    const int k = tid;
    const int K16 = k >> 4, kk = k & 15;
    const int lo = kk & 1, tt = (kk >> 1) & 3, hi = kk >> 3;
    {   // A-perm
        int R = row >> 4, rr = row & 15, wh = rr >> 3, g = rr & 7;
        int s4 = hi * 2 + wh;
        g_fnA[((size_t)(R * 16 + K16) * 128 + (g * 4 + tt) * 4 + s4) * 2 + lo] = h;
    }
    {   // B-perm
        int N8 = row >> 3, g = row & 7;
        g_fnB[((size_t)(N8 * 16 + K16) * 64 + (g * 4 + tt) * 2 + hi) * 2 + lo] = h;
    }
}

// ---------------------------------------------------------------------------
// K1: symmetric fp16 GEMM (fp32 accum), upper-triangular CTA tiles only.
// Fused epilogue identical to R6: smem-staged coalesced logit stores (direct
// + mirror), perfect_logit, deterministic row/col partials.
// ---------------------------------------------------------------------------
__global__ __launch_bounds__(256, 2)
void gemm_tc(const int* __restrict__ labels,
             float* __restrict__ out_logits,
             float* __restrict__ out_perfect) {
    const int J = blockIdx.x;            // colblock
    const int I = blockIdx.y;            // rowblock
    if (J < I) return;
    const bool isDiag = (I == J);

    // sbuf: mainloop: sA stage s at +s*2048, sB at +4096+s*2048 (uint32 units);
    //       epilogue: 64x132 float staging tile.
    __shared__ float sbuf[8448];
    __shared__ int   labR[BM];
    __shared__ int   labC[BN];
    __shared__ float sred[4][3][BM];
    __shared__ float sredC[2][3][BN];

    const int tid  = threadIdx.x;
    const int lane = tid & 31;
    const int wid  = tid >> 5;
    const int warp_m = wid & 1;
    const int warp_n = wid >> 1;
    const int rowBase = I * BM;
    const int colBase = J * BN;
    const int g = lane >> 2, t = lane & 3;

    if (tid < 128) labR[tid] = labels[rowBase + tid];
    else           labC[tid - 128] = labels[colBase + tid - 128];

    float c[4][4][4];
    #pragma unroll
    for (int mi = 0; mi < 4; mi++)
        #pragma unroll
        for (int ni = 0; ni < 4; ni++)
            #pragma unroll
            for (int q = 0; q < 4; q++) c[mi][ni][q] = 0.0f;

    const int rB16 = rowBase >> 4;       // A row-block base (16-row blocks)
    const int cB8  = colBase >> 3;       // B n-block base (8-row blocks)

    // Stage: A = 16 blocks (8 r16 x 2 K16) x 512B; B = 32 blocks (16 n8 x 2 K16) x 256B.
    auto fill = [&](int s, int kt) {
        uint32_t sAu = smem_u32(&sbuf[s * 2048]);
        uint32_t sBu = smem_u32(&sbuf[4096 + s * 2048]);
        #pragma unroll
        for (int i = 0; i < 2; i++) {
            int ca = tid + i * 256;               // 0..511
            int blk = ca >> 5, w = ca & 31;       // A: blk = r16b*2 + K16l
            int gblk = (rB16 + (blk >> 1)) * 16 + kt * 2 + (blk & 1);
            cp_async16(sAu + blk * 512 + w * 16,
                       (const char*)g_fnA + (size_t)gblk * 512 + w * 16);
            int bblk = ca >> 4, bw = ca & 15;     // B: bblk = n8b*2 + K16l
            int gbb = (cB8 + (bblk >> 1)) * 16 + kt * 2 + (bblk & 1);
            cp_async16(sBu + bblk * 256 + bw * 16,
                       (const char*)g_fnB + (size_t)gbb * 256 + bw * 16);
        }
    };

    fill(0, 0); CP_COMMIT();
    fill(1, 1); CP_COMMIT();

    #pragma unroll 1
    for (int kt = 0; kt < NKT; kt++) {
        if (kt < NKT - 1) { CP_WAIT(1); } else { CP_WAIT(0); }
        __syncthreads();
        const int s = kt & 1;
        #pragma unroll
        for (int ks = 0; ks < 2; ks++) {          // two K16 steps
            uint32_t a[4][4], b[4][2];
            #pragma unroll
            for (int mi = 0; mi < 4; mi++) {
                const float4 va = *(const float4*)&sbuf[s * 2048 + ((warp_m * 4 + mi) * 2 + ks) * 128 + lane * 4];
                a[mi][0] = __float_as_uint(va.x); a[mi][1] = __float_as_uint(va.y);
                a[mi][2] = __float_as_uint(va.z); a[mi][3] = __float_as_uint(va.w);
            }
            #pragma unroll
            for (int ni = 0; ni < 4; ni++) {
                const float2 vb = *(const float2*)&sbuf[4096 + s * 2048 + ((warp_n * 4 + ni) * 2 + ks) * 64 + lane * 2];
                b[ni][0] = __float_as_uint(vb.x); b[ni][1] = __float_as_uint(vb.y);
            }
            #pragma unroll
            for (int mi = 0; mi < 4; mi++)
                #pragma unroll
                for (int ni = 0; ni < 4; ni++)
                    mma_f16(c[mi][ni], a[mi], b[ni]);
        }
        __syncthreads();
        if (kt + 2 < NKT) { fill(kt & 1, kt + 2); CP_COMMIT(); }
    }

    // ---------------- Fused epilogue (identical to R6) ----------------
    #pragma unroll
    for (int mi = 0; mi < 4; mi++)
        #pragma unroll
        for (int ni = 0; ni < 4; ni++)
            #pragma unroll
            for (int q = 0; q < 4; q++) c[mi][ni][q] *= 10.0f;

    float cD[4][2], cP[4][2], cC[4][2];
    #pragma unroll
    for (int ni = 0; ni < 4; ni++)
        #pragma unroll
        for (int q = 0; q < 2; q++) { cD[ni][q] = 0.f; cP[ni][q] = 0.f; cC[ni][q] = 0.f; }

    #pragma unroll
    for (int mi = 0; mi < 4; mi++) {
        const int r0l = warp_m * 64 + mi * 16 + g;
        const int r1l = r0l + 8;
        const int gr0 = rowBase + r0l, gr1 = rowBase + r1l;
        const int lab0 = labR[r0l], lab1 = labR[r1l];
        float d0 = 0.f, p0 = 0.f, n0 = 0.f, d1 = 0.f, p1 = 0.f, n1 = 0.f;
        #pragma unroll
        for (int ni = 0; ni < 4; ni++) {
            const int cl = warp_n * 32 + ni * 8 + 2 * t;
            const int gc = colBase + cl;
            const float v00 = c[mi][ni][0], v01 = c[mi][ni][1];
            const float v10 = c[mi][ni][2], v11 = c[mi][ni][3];
            const int lc0 = labC[cl], lc1 = labC[cl + 1];
            const float e00 = __expf(v00), e01 = __expf(v01);
            const float e10 = __expf(v10), e11 = __expf(v11);
            if (gc != gr0)     { d0 += e00; if (lc0 == lab0) { p0 += v00; n0 += 1.f; } }
            if (gc + 1 != gr0) { d0 += e01; if (lc1 == lab0) { p0 += v01; n0 += 1.f; } }
            if (gc != gr1)     { d1 += e10; if (lc0 == lab1) { p1 += v10; n1 += 1.f; } }
            if (gc + 1 != gr1) { d1 += e11; if (lc1 == lab1) { p1 += v11; n1 += 1.f; } }
            if (!isDiag) {
                cD[ni][0] += e00 + e10;
                cD[ni][1] += e01 + e11;
                if (lc0 == lab0) { cP[ni][0] += v00; cC[ni][0] += 1.f; }
                if (lc0 == lab1) { cP[ni][0] += v10; cC[ni][0] += 1.f; }
                if (lc1 == lab0) { cP[ni][1] += v01; cC[ni][1] += 1.f; }
                if (lc1 == lab1) { cP[ni][1] += v11; cC[ni][1] += 1.f; }
            }
        }
        #pragma unroll
        for (int o = 1; o <= 2; o <<= 1) {
            d0 += __shfl_xor_sync(0xffffffffu, d0, o);
            p0 += __shfl_xor_sync(0xffffffffu, p0, o);
            n0 += __shfl_xor_sync(0xffffffffu, n0, o);
            d1 += __shfl_xor_sync(0xffffffffu, d1, o);
            p1 += __shfl_xor_sync(0xffffffffu, p1, o);
            n1 += __shfl_xor_sync(0xffffffffu, n1, o);
        }
        if (t == 0) {
            sred[warp_n][0][r0l] = d0; sred[warp_n][1][r0l] = p0; sred[warp_n][2][r0l] = n0;
            sred[warp_n][0][r1l] = d1; sred[warp_n][1][r1l] = p1; sred[warp_n][2][r1l] = n1;
        }
    }

    if (!isDiag) {
        #pragma unroll
        for (int ni = 0; ni < 4; ni++)
            #pragma unroll
            for (int q = 0; q < 2; q++) {
                #pragma unroll
                for (int o = 4; o <= 16; o <<= 1) {
                    cD[ni][q] += __shfl_xor_sync(0xffffffffu, cD[ni][q], o);
                    cP[ni][q] += __shfl_xor_sync(0xffffffffu, cP[ni][q], o);
                    cC[ni][q] += __shfl_xor_sync(0xffffffffu, cC[ni][q], o);
                }
            }
        if (lane < 4) {
            #pragma unroll
            for (int ni = 0; ni < 4; ni++) {
                int cl = warp_n * 32 + ni * 8 + 2 * t;
                sredC[warp_m][0][cl]     = cD[ni][0];
                sredC[warp_m][1][cl]     = cP[ni][0];
                sredC[warp_m][2][cl]     = cC[ni][0];
                sredC[warp_m][0][cl + 1] = cD[ni][1];
                sredC[warp_m][1][cl + 1] = cP[ni][1];
                sredC[warp_m][2][cl + 1] = cC[ni][1];
            }
        }
    }
    __syncthreads();

    if (tid < BM) {
        float D = 0.f, P = 0.f, C = 0.f;
        #pragma unroll
        for (int wn = 0; wn < 4; wn++) {
            D += sred[wn][0][tid]; P += sred[wn][1][tid]; C += sred[wn][2][tid];
        }
        const size_t slot = (size_t)J * NROWS + rowBase + tid;
        g_denp[slot] = D; g_posp[slot] = P; g_cntp[slot] = C;
    } else if (!isDiag) {
        const int jc = tid - 128;
        const float D = sredC[0][0][jc] + sredC[1][0][jc];
        const float P = sredC[0][1][jc] + sredC[1][1][jc];
        const float C = sredC[0][2][jc] + sredC[1][2][jc];
        const size_t slot = (size_t)I * NROWS + colBase + jc;
        g_denp[slot] = D; g_posp[slot] = P; g_cntp[slot] = C;
    }

    // ---- Direct logits tile via smem staging ----
    #pragma unroll 1
    for (int h = 0; h < 2; h++) {
        __syncthreads();
        if (warp_m == h) {
            #pragma unroll
            for (int mi = 0; mi < 4; mi++)
                #pragma unroll
                for (int ni = 0; ni < 4; ni++)
                    #pragma unroll
                    for (int q = 0; q < 4; q++) {
                        int rl = mi * 16 + g + 8 * (q >> 1);
                        int cl = warp_n * 32 + ni * 8 + 2 * t + (q & 1);
                        sbuf[rl * 132 + cl] = c[mi][ni][q];
                    }
        }
        __syncthreads();
        #pragma unroll 8
        for (int it = 0; it < 32; it++) {
            int idx = tid + it * 256;
            int rr = idx >> 7, cc = idx & 127;
            out_logits[(size_t)(rowBase + h * 64 + rr) * NROWS + colBase + cc] = sbuf[rr * 132 + cc];
        }
    }

    // ---- Mirror logits tile (transposed) via smem staging ----
    if (!isDiag) {
        #pragma unroll 1
        for (int p = 0; p < 2; p++) {
            __syncthreads();
            if ((warp_n >> 1) == p) {
                #pragma unroll
                for (int mi = 0; mi < 4; mi++)
                    #pragma unroll
                    for (int ni = 0; ni < 4; ni++)
                        #pragma unroll
                        for (int q = 0; q < 4; q++) {
                            int cl = (warp_n & 1) * 32 + ni * 8 + 2 * t + (q & 1);
                            int rl = warp_m * 64 + mi * 16 + g + 8 * (q >> 1);
                            sbuf[cl * 132 + rl] = c[mi][ni][q];
                        }
            }
            __syncthreads();
            #pragma unroll 8
            for (int it = 0; it < 32; it++) {
                int idx = tid + it * 256;
                int rr = idx >> 7, cc = idx & 127;
                out_logits[(size_t)(colBase + p * 64 + rr) * NROWS + rowBase + cc] = sbuf[rr * 132 + cc];
            }
        }
    }

    // perfect_logit tile(s)
    #pragma unroll 8
    for (int i = 0; i < 64; i++) {
        int idx = tid + i * 256;
        int rr = idx >> 7;
        int jc = idx & 127;
        out_perfect[(size_t)(rowBase + rr) * NROWS + colBase + jc] =
            (labR[rr] == labC[jc]) ? 1.0f : -1.0f;
    }
    if (!isDiag) {
        #pragma unroll 8
        for (int i = 0; i < 64; i++) {
            int idx = tid + i * 256;
            int rr = idx >> 7;
            int jc = idx & 127;
            out_perfect[(size_t)(colBase + rr) * NROWS + rowBase + jc] =
                (labC[rr] == labR[jc]) ? 1.0f : -1.0f;
        }
    }
}

// ---------------------------------------------------------------------------
// K2: reduce partials -> per-row value (deterministic order).
// ---------------------------------------------------------------------------
__global__ void rowfinal_kernel() {
    int i = blockIdx.x * 256 + threadIdx.x;
    float D = 0.f, P = 0.f, C = 0.f;
    #pragma unroll 4
    for (int b = 0; b < NCOLB; b++) {
        D += g_denp[(size_t)b * NROWS + i];
        P += g_posp[(size_t)b * NROWS + i];
        C += g_cntp[(size_t)b * NROWS + i];
    }
    g_rowval[i] = -(P - C * logf(D)) / (C + 1e-6f);
}

// ---------------------------------------------------------------------------
// K3: loss = mean(rowval)
// ---------------------------------------------------------------------------
__global__ void loss_kernel(float* __restrict__ out) {
    const int tid = threadIdx.x;                 // 1024
    float s = 0.0f;
    for (int i = tid; i < NROWS; i += 1024) s += g_rowval[i];
    __shared__ float rd[32];
    #pragma unroll
    for (int o = 16; o > 0; o >>= 1) s += __shfl_xor_sync(0xffffffffu, s, o);
    if ((tid & 31) == 0) rd[tid >> 5] = s;
    __syncthreads();
    if (tid < 32) {
        float v = rd[tid];
        #pragma unroll
        for (int o = 16; o > 0; o >>= 1) v += __shfl_xor_sync(0xffffffffu, v, o);
        if (tid == 0) out[0] = v / (float)NROWS;
    }
}

// ---------------------------------------------------------------------------
// Launch: out = [loss(1) | logits(8192^2) | perfect_logit(8192^2)]
// ---------------------------------------------------------------------------
extern "C" void kernel_launch(void* const* d_in, const int* in_sizes, int n_in,
                              void* d_out, int out_size) {
    const float* features = (const float*)d_in[0];
    const int*   labels   = (const int*)d_in[1];
    float* out         = (float*)d_out;
    float* out_logits  = out + 1;
    float* out_perfect = out + 1 + (size_t)NROWS * NROWS;

    normalize_kernel<<<NROWS, 256>>>(features);
    dim3 grid(NCOLB, NROWB);                     // 64 x 64, lower triangle exits
    gemm_tc<<<grid, 256>>>(labels, out_logits, out_perfect);
    rowfinal_kernel<<<NROWS / 256, 256>>>();
    loss_kernel<<<1, 1024>>>(out);
}